// round 16
// baseline (speedup 1.0000x reference)
#include <cuda_runtime.h>
#include <math.h>

// SmoothDCGLoss via tensor-Chebyshev projection of sigmoid(s - t).
// rank_j(b) = sum_i sigmoid(s_bi - t_bj)
//           = sum_q [ sum_p A_pq * M_p(b) ] * T_q(t_bj / SB)
// where M_p(b) = sum_i T_p(s_bi / SA)   (the only O(N) work, pure FMA).
//
// R16: TMA bulk staging. R12-R15 all plateaued at 2.0-2.45 TB/s HBM across
// very different schedules -> per-SM L1tex wavefront-queue cap on
// thread-issued loads (~8KB in flight/SM). cp.async.bulk (UBLKCP) bypasses
// that queue via the TMA engine (chip LTS cap ~6300 B/cyc, path-indep).
// Pipeline: 8 stages x 12KB, 3-slot ring, mbarrier complete_tx, issue 2
// ahead, elected-thread producer. Compute core / P=10 / ticket epilogue
// frozen from R15.

#define BATCH   256
#define NCOL    50000
#define TOPK    20
#define P_DEG   10
#define Q_DEG   32
#define SA      6.0
#define SB      5.0
#define NG      64
#define CHUNKS  2
#define CHUNK_ELEMS (NCOL/CHUNKS)      // 25000 floats
#define CHUNK_VEC   (CHUNK_ELEMS/4)    // 6250 float4s = 8*768 + 106
#define STAGE_VEC   768                // float4s per stage (12 KB)
#define STAGE_BYTES (STAGE_VEC*16)
#define NSTAGES     8
#define RING        3
#define REMAIN      (CHUNK_VEC - NSTAGES*STAGE_VEC)   // 106
#define NACC        (P_DEG-1)          // moments k=1..9 (M_0 = N exact)

typedef unsigned long long ull;

struct CoefArg {
    float A[P_DEG][Q_DEG];   // Chebyshev tensor coefficients
    float idcg[TOPK];        // cumulative 1/log2(i+2)
};

__device__ float g_part[BATCH*CHUNKS][P_DEG];
__device__ unsigned int g_ticket[BATCH];   // zero-initialized; reset after use

__device__ __forceinline__ ull pack2(float lo, float hi) {
    ull r; asm("mov.b64 %0,{%1,%2};" : "=l"(r) : "f"(lo), "f"(hi)); return r;
}
__device__ __forceinline__ void unpack2(ull v, float& lo, float& hi) {
    asm("mov.b64 {%0,%1},%2;" : "=f"(lo), "=f"(hi) : "l"(v));
}
__device__ __forceinline__ ull f2fma(ull a, ull b, ull c) {
    ull d; asm("fma.rn.f32x2 %0,%1,%2,%3;" : "=l"(d) : "l"(a), "l"(b), "l"(c)); return d;
}
__device__ __forceinline__ ull f2add(ull a, ull b) {
    ull d; asm("add.rn.f32x2 %0,%1,%2;" : "=l"(d) : "l"(a), "l"(b)); return d;
}
__device__ __forceinline__ ull f2mul(ull a, ull b) {
    ull d; asm("mul.rn.f32x2 %0,%1,%2;" : "=l"(d) : "l"(a), "l"(b)); return d;
}

__device__ __forceinline__ unsigned int smem_u32(const void* p) {
    return (unsigned int)__cvta_generic_to_shared(p);
}
__device__ __forceinline__ void mbar_init(unsigned int mbar, unsigned int cnt) {
    asm volatile("mbarrier.init.shared.b64 [%0], %1;" :: "r"(mbar), "r"(cnt) : "memory");
}
__device__ __forceinline__ void mbar_expect_tx(unsigned int mbar, unsigned int bytes) {
    asm volatile("mbarrier.arrive.expect_tx.shared.b64 _, [%0], %1;"
                 :: "r"(mbar), "r"(bytes) : "memory");
}
__device__ __forceinline__ void bulk_g2s(unsigned int dst, const void* src,
                                         unsigned int bytes, unsigned int mbar) {
    asm volatile(
        "cp.async.bulk.shared::cluster.global.mbarrier::complete_tx::bytes "
        "[%0], [%1], %2, [%3];"
        :: "r"(dst), "l"(src), "r"(bytes), "r"(mbar) : "memory");
}
__device__ __forceinline__ void mbar_wait(unsigned int mbar, unsigned int parity) {
    asm volatile(
        "{\n\t"
        ".reg .pred P1;\n\t"
        "WAIT_%=:\n\t"
        "mbarrier.try_wait.parity.acquire.cta.shared::cta.b64 P1, [%0], %1, 0x989680;\n\t"
        "@P1 bra.uni DONE_%=;\n\t"
        "bra.uni WAIT_%=;\n\t"
        "DONE_%=:\n\t"
        "}"
        :: "r"(mbar), "r"(parity) : "memory");
}

// Packed period-4 Chebyshev recurrence for one lane (2 elements).
// H_0=1, H_1=u, H_{k+1} = fma(k odd ? -2u : +2u, H_k, H_{k-1}); H_k=sigma_k T_k.
struct Lane {
    ull vp, vm, hp, hc;
    __device__ __forceinline__ void init(float s0, float s1, ull ones, ull scale2) {
        float c0 = fminf((float)SA, fmaxf(-(float)SA, s0));
        float c1 = fminf((float)SA, fmaxf(-(float)SA, s1));
        vp = f2mul(pack2(c0, c1), scale2);   // 2u
        vm = vp ^ 0x8000000080000000ull;     // -2u (LOP3, ALU pipe)
        hp = ones;                           // H_0
        hc = f2mul(vp, pack2(0.5f, 0.5f));   // H_1 = u
    }
    __device__ __forceinline__ ull step(int k) {   // returns H_{k+1}
        ull hn = f2fma((k & 1) ? vm : vp, hc, hp);
        hp = hc; hc = hn; return hn;
    }
};

// One float4 (2 packed lanes): only 2 Lane structs live at a time.
__device__ __forceinline__ void compute2(const float4& t0, ull* acc,
                                         ull ones, ull scale2) {
    Lane A, B;
    A.init(t0.x, t0.y, ones, scale2);
    B.init(t0.z, t0.w, ones, scale2);
    acc[0] = f2add(acc[0], f2add(A.hc, B.hc));
#pragma unroll
    for (int k = 1; k < NACC; k++) {
        ull a = A.step(k), bb = B.step(k);
        acc[k] = f2add(acc[k], f2add(a, bb));
    }
}

__global__ void __launch_bounds__(256, 4) fused_kernel(
        const float* __restrict__ scores,
        const float* __restrict__ stop,
        const float* __restrict__ labels,
        float* __restrict__ out,
        const __grid_constant__ CoefArg cf) {
    __shared__ float4 ring[RING][STAGE_VEC];     // 36 KB
    __shared__ ull    mbars[RING];
    int b = blockIdx.x >> 1;
    int c = blockIdx.x & 1;
    const float4* src = reinterpret_cast<const float4*>(
        scores + (size_t)b * NCOL + (size_t)c * CHUNK_ELEMS);
    int t = threadIdx.x;

    const ull ones   = pack2(1.0f, 1.0f);
    const ull scale2 = pack2((float)(2.0 / SA), (float)(2.0 / SA));

    unsigned int mb0 = smem_u32(&mbars[0]);
    unsigned int rg0 = smem_u32(&ring[0][0]);

    if (t == 0) {
        mbar_init(mb0,      1);
        mbar_init(mb0 + 8,  1);
        mbar_init(mb0 + 16, 1);
        asm volatile("fence.proxy.async.shared::cta;" ::: "memory");
    }

    // Remainder prefetch into registers (consumed at the very end).
    float4 rem = make_float4(0.f, 0.f, 0.f, 0.f);
    if (t < REMAIN) rem = __ldg(&src[NSTAGES * STAGE_VEC + t]);

    ull acc[NACC];
#pragma unroll
    for (int k = 0; k < NACC; k++) acc[k] = 0ull;  // bits of (0.f,0.f)

    __syncthreads();   // mbar init visible to all before any wait/TMA

#define ISSUE(J) do {                                                        \
        unsigned int s_ = (J) % RING;                                        \
        mbar_expect_tx(mb0 + 8 * s_, STAGE_BYTES);                           \
        bulk_g2s(rg0 + s_ * STAGE_BYTES,                                     \
                 (const char*)src + (size_t)(J) * STAGE_BYTES,               \
                 STAGE_BYTES, mb0 + 8 * s_);                                 \
    } while (0)

    if (t == 0) { ISSUE(0); ISSUE(1); }

#pragma unroll
    for (int j = 0; j < NSTAGES; j++) {
        int slot = j % RING;
        unsigned int par = (j / RING) & 1;
        mbar_wait(mb0 + 8 * slot, par);
        // All threads past wait(j) have finished reading stage j-1 (program
        // order), so after this barrier slot (j-1)%RING == (j+2)%RING is free.
        __syncthreads();
        if (t == 0 && j + 2 < NSTAGES) ISSUE(j + 2);
#pragma unroll
        for (int q = 0; q < 3; q++) {
            float4 v = ring[slot][t + 256 * q];
            compute2(v, acc, ones, scale2);
        }
    }

    // Remainder: threads 0..105 process their prefetched float4.
    if (t < REMAIN)
        compute2(rem, acc, ones, scale2);

    // Unpack + sign fix: acc[j] holds H_{j+1}; moment k=j+1 = sigma_k H_k,
    // sigma_k = -1 iff (k & 2).
    float m[NACC];
#pragma unroll
    for (int j = 0; j < NACC; j++) {
        float lo, hi; unpack2(acc[j], lo, hi);
        float s = lo + hi;
        m[j] = ((j + 1) & 2) ? -s : s;
    }

#pragma unroll
    for (int j = 0; j < NACC; j++)
#pragma unroll
        for (int off = 16; off > 0; off >>= 1)
            m[j] += __shfl_xor_sync(0xffffffffu, m[j], off);

    __shared__ float red[8][P_DEG];
    int warp = threadIdx.x >> 5, lane = threadIdx.x & 31;
    if (lane == 0) {
#pragma unroll
        for (int j = 0; j < NACC; j++) red[warp][j + 1] = m[j];
    }
    __syncthreads();
    if (threadIdx.x >= 1 && threadIdx.x < P_DEG) {
        float s = 0.0f;
        for (int w = 0; w < 8; w++) s += red[w][threadIdx.x];
        g_part[blockIdx.x][threadIdx.x] = s;
    }

    // ---- ticket: last chunk block of batch b runs the epilogue ----
    __threadfence();
    __shared__ unsigned int ticket_s;
    if (threadIdx.x == 0)
        ticket_s = atomicAdd(&g_ticket[b], 1u);
    __syncthreads();
    if (ticket_s != CHUNKS - 1) return;

    __threadfence();                   // make peer g_part writes visible
    if (threadIdx.x == 0)
        atomicExch(&g_ticket[b], 0u);  // reset for next graph replay

    __shared__ float Msh[P_DEG], Csh[Q_DEG];
    __shared__ float dg_sh[TOPK], lb_sh[TOPK];
    int tid = threadIdx.x;

    if (tid < P_DEG) {
        if (tid == 0) {
            Msh[0] = (float)NCOL;      // M_0 exact
        } else {
            float s = 0.0f;
            for (int cc = 0; cc < CHUNKS; cc++)
                s += g_part[b * CHUNKS + cc][tid];
            Msh[tid] = s;
        }
    }
    __syncthreads();

    if (tid < Q_DEG) {
        float s = 0.0f;
#pragma unroll
        for (int p = 0; p < P_DEG; p++) s = fmaf(cf.A[p][tid], Msh[p], s);
        Csh[tid] = s;
    }
    __syncthreads();

    if (tid < TOPK) {
        float tt = stop[b * TOPK + tid];
        float v = fminf(1.0f, fmaxf(-1.0f, tt * (float)(1.0 / SB)));
        float b1 = 0.0f, b2 = 0.0f;
        for (int q = Q_DEG - 1; q >= 1; q--) {
            float bn = fmaf(2.0f * v, b1, Csh[q]) - b2;
            b2 = b1; b1 = bn;
        }
        float rank = fmaf(v, b1, Csh[0]) - b2 + 0.5f;
        float d = log2f(rank + 1.0f);
        float lb = labels[b * TOPK + tid];
        dg_sh[tid] = lb / d;
        lb_sh[tid] = lb;
    }
    __syncthreads();

    if (tid < TOPK) {
        float dcg = 0.0f;
        for (int i2 = 0; i2 <= tid; i2++) dcg += dg_sh[i2];
        float ks = 0.0f;
        for (int i2 = 0; i2 < TOPK; i2++) ks += lb_sh[i2];
        int k = (int)(ks + 0.5f);
        int kc = min(k, tid + 1);
        int idx = kc - 1;
        if (idx < 0) idx = TOPK - 1;   // jnp negative-index wrap
        out[b * TOPK + tid] = dcg / cf.idcg[idx];
    }
}

// ---------------------------------------------------------------------------
// Host: Chebyshev-Gauss collocation for A_pq in double precision.
// Pure CPU math (libm only) — runs outside the timed graph replay.
// ---------------------------------------------------------------------------
static void compute_coefs(CoefArg* cf) {
    static double fv[NG][NG];
    static double Hm[P_DEG][NG];
    const double PI = 3.14159265358979323846;

    double xs[NG];
    for (int a = 0; a < NG; a++)
        xs[a] = cos(PI * (2.0 * a + 1.0) / (2.0 * NG));
    for (int a = 0; a < NG; a++)
        for (int bb = 0; bb < NG; bb++) {
            double d = SA * xs[a] - SB * xs[bb];
            fv[a][bb] = 1.0 / (1.0 + exp(-d));
        }
    for (int p = 0; p < P_DEG; p++)
        for (int bb = 0; bb < NG; bb++) {
            double s = 0.0;
            for (int a = 0; a < NG; a++)
                s += cos(PI * p * (2.0 * a + 1.0) / (2.0 * NG)) * fv[a][bb];
            Hm[p][bb] = s;
        }
    for (int p = 0; p < P_DEG; p++)
        for (int q = 0; q < Q_DEG; q++) {
            double s = 0.0;
            for (int bb = 0; bb < NG; bb++)
                s += Hm[p][bb] * cos(PI * q * (2.0 * bb + 1.0) / (2.0 * NG));
            double w = ((p == 0) ? 1.0 : 2.0) * ((q == 0) ? 1.0 : 2.0)
                       / ((double)NG * (double)NG);
            cf->A[p][q] = (float)(w * s);
        }
    double acc = 0.0;
    for (int i = 0; i < TOPK; i++) {
        acc += 1.0 / (log(i + 2.0) / log(2.0));
        cf->idcg[i] = (float)acc;
    }
}

extern "C" void kernel_launch(void* const* d_in, const int* in_sizes, int n_in,
                              void* d_out, int out_size) {
    const float* stop   = (const float*)d_in[0];  // scores_top (256,20)
    const float* scores = (const float*)d_in[1];  // scores     (256,50000)
    const float* labels = (const float*)d_in[2];  // labels     (256,20)
    float* out = (float*)d_out;                   // ndcg       (256,20) f32

    static CoefArg cf;
    compute_coefs(&cf);   // pure host math, identical result every call

    fused_kernel<<<BATCH * CHUNKS, 256>>>(scores, stop, labels, out, cf);
}